// round 16
// baseline (speedup 1.0000x reference)
#include <cuda_runtime.h>
#include <cuda_bf16.h>
#include <cstdint>

#define NUM_HEADS 16
#define HEAD_DIM  64
#define B_SZ      4
#define SEQ       2048
#define DIM       1024

// Scratch (no cudaMalloc allowed).
__device__ __nv_bfloat16 g_Qb[B_SZ * SEQ * DIM];   // [B,H,S,D] bf16
__device__ __nv_bfloat16 g_Kb[B_SZ * SEQ * DIM];   // [B,H,S,D] bf16
__device__ __nv_bfloat16 g_Vt[B_SZ * SEQ * DIM];   // [B,H,D,S] bf16 (transposed)
__device__ float g_Wr[3 * DIM * DIM];              // RNA-rounded weights (q,k,v)

__device__ __forceinline__ float f2tf32f(float x) {
    uint32_t u;
    asm("cvt.rna.tf32.f32 %0, %1;" : "=r"(u) : "f"(x));
    return __uint_as_float(u);
}
__device__ __forceinline__ uint32_t f2tf32u(float x) {
    uint32_t u;
    asm("cvt.rna.tf32.f32 %0, %1;" : "=r"(u) : "f"(x));
    return u;
}
__device__ __forceinline__ uint32_t smem_u32(const void* p) {
    uint32_t a;
    asm("{ .reg .u64 t; cvta.to.shared.u64 t, %1; cvt.u32.u64 %0, t; }" : "=r"(a) : "l"(p));
    return a;
}
// .cg: bypass L1 (streaming data, zero L1 reuse — don't pollute the cache).
__device__ __forceinline__ void cp16(uint32_t s, const void* g) {
    asm volatile("cp.async.cg.shared.global [%0], [%1], 16;" :: "r"(s), "l"(g));
}
#define CP_COMMIT() asm volatile("cp.async.commit_group;" ::: "memory")
#define CP_WAIT(n)  asm volatile("cp.async.wait_group %0;" :: "n"(n) : "memory")

// tf32 MMA m16n8k8 (A row, B col), fp32 accum in place.
__device__ __forceinline__ void mma_tf32(float d[4], const uint32_t a[4], const uint32_t b[2]) {
    asm volatile(
        "mma.sync.aligned.m16n8k8.row.col.f32.tf32.tf32.f32 "
        "{%0,%1,%2,%3}, {%4,%5,%6,%7}, {%8,%9}, {%0,%1,%2,%3};"
        : "+f"(d[0]), "+f"(d[1]), "+f"(d[2]), "+f"(d[3])
        : "r"(a[0]), "r"(a[1]), "r"(a[2]), "r"(a[3]), "r"(b[0]), "r"(b[1]));
}
// bf16 MMA m16n8k16 (A row, B col), fp32 accum in place.
__device__ __forceinline__ void mma_bf16(float d[4], const uint32_t a[4], const uint32_t b[2]) {
    asm volatile(
        "mma.sync.aligned.m16n8k16.row.col.f32.bf16.bf16.f32 "
        "{%0,%1,%2,%3}, {%4,%5,%6,%7}, {%8,%9}, {%0,%1,%2,%3};"
        : "+f"(d[0]), "+f"(d[1]), "+f"(d[2]), "+f"(d[3])
        : "r"(a[0]), "r"(a[1]), "r"(a[2]), "r"(a[3]), "r"(b[0]), "r"(b[1]));
}
__device__ __forceinline__ uint32_t pack_bf16x2(float lo, float hi) {
    __nv_bfloat162 p = __float22bfloat162_rn(make_float2(lo, hi));
    return *(uint32_t*)&p;
}

// ===========================================================================
// Fused RNA tf32 rounding copy for all three weights (12MB total).
// ===========================================================================
__global__ __launch_bounds__(256) void round_copy3_kernel(
    const float4* __restrict__ s0, const float4* __restrict__ s1,
    const float4* __restrict__ s2, float4* __restrict__ dst, int n4)
{
    const int total = 3 * n4;
    for (int i = blockIdx.x * 256 + threadIdx.x; i < total; i += gridDim.x * 256) {
        const int which = i / n4;
        const int j = i - which * n4;
        const float4* src = (which == 0) ? s0 : ((which == 1) ? s1 : s2);
        float4 v = src[j];
        v.x = f2tf32f(v.x); v.y = f2tf32f(v.y);
        v.z = f2tf32f(v.z); v.w = f2tf32f(v.w);
        dst[i] = v;
    }
}

// ===========================================================================
// Fused projection GEMM (blockIdx.z = which), tf32 mma.sync.
// 3-stage cp.async ring (.cg), ONE syncthreads per K-step (stage after
// barrier — slot s+2 was last read in step s-1, separated by barrier s).
// Outputs bf16: Q,K -> [B,H,S,D]; V -> [B,H,D,S] (transposed) with ReLU.
// ===========================================================================
#define PA_ST 36
#define PB_ST 136
#define PJ_ABUF (128 * PA_ST)
#define PJ_BBUF (32 * PB_ST)
#define PJ_NBUF 3
#define PJ_SMEM ((PJ_NBUF * PJ_ABUF + PJ_NBUF * PJ_BBUF) * 4)   // 107520 B

__global__ __launch_bounds__(256, 2) void proj_mma_kernel(
    const float* __restrict__ q, const float* __restrict__ k,
    const float* __restrict__ v,
    const float* __restrict__ bq, const float* __restrict__ bk,
    const float* __restrict__ bv)
{
    extern __shared__ float psm[];
    float* As = psm;                                 // 3 x 128 x 36
    float* Bs = psm + PJ_NBUF * PJ_ABUF;             // 3 x 32 x 136

    const int which = blockIdx.z;
    const float* A    = (which == 0) ? q  : ((which == 1) ? k  : v);
    const float* bias = (which == 0) ? bq : ((which == 1) ? bk : bv);
    const float* W    = g_Wr + (size_t)which * DIM * DIM;

    const int tid  = threadIdx.x;
    const int wid  = tid >> 5;
    const int lane = tid & 31;
    const int g    = lane >> 2;
    const int t    = lane & 3;
    const int warpM = wid >> 1;
    const int warpN = wid & 1;
    const int rowBase = blockIdx.y * 128;
    const int colBase = blockIdx.x * 128;

    float acc[2][8][4];
#pragma unroll
    for (int mi = 0; mi < 2; mi++)
#pragma unroll
        for (int nt = 0; nt < 8; nt++)
#pragma unroll
            for (int j = 0; j < 4; j++) acc[mi][nt][j] = 0.f;

    const uint32_t asb = smem_u32(As);
    const uint32_t bsb = smem_u32(Bs);

    auto stage = [&](int slot, int k0) {
#pragma unroll
        for (int i = 0; i < 4; i++) {
            const int idx = tid + i * 256;
            const int r  = idx >> 3;
            const int c4 = (idx & 7) << 2;
            cp16(asb + (slot * PJ_ABUF + r * PA_ST + c4) * 4,
                 &A[(size_t)(rowBase + r) * DIM + k0 + c4]);
        }
#pragma unroll
        for (int i = 0; i < 4; i++) {
            const int idx = tid + i * 256;
            const int r  = idx >> 5;
            const int c4 = (idx & 31) << 2;
            cp16(bsb + (slot * PJ_BBUF + r * PB_ST + c4) * 4,
                 &W[(size_t)(k0 + r) * DIM + colBase + c4]);
        }
        CP_COMMIT();
    };

    stage(0, 0);
    stage(1, 32);

    const int m0 = warpM * 32;
    const int n0 = warpN * 64;
    const int NSTEP = DIM / 32;   // 32

    for (int step = 0; step < NSTEP; ++step) {
        if (step < NSTEP - 1) { CP_WAIT(1); } else { CP_WAIT(0); }
        __syncthreads();
        if (step + 2 < NSTEP) stage((step + 2) % PJ_NBUF, (step + 2) * 32);

        const int slot = step % PJ_NBUF;
        const float* Ab = As + slot * PJ_ABUF;
        const float* Bb = Bs + slot * PJ_BBUF;

#pragma unroll
        for (int kk = 0; kk < 4; ++kk) {
            uint32_t af[2][4];
#pragma unroll
            for (int mi = 0; mi < 2; mi++) {
                const float* ar0 = &Ab[(m0 + mi * 16 + g) * PA_ST + kk * 8 + t];
                const float* ar1 = &Ab[(m0 + mi * 16 + g + 8) * PA_ST + kk * 8 + t];
                af[mi][0] = f2tf32u(ar0[0]);
                af[mi][1] = f2tf32u(ar1[0]);
                af[mi][2] = f2tf32u(ar0[4]);
                af[mi][3] = f2tf32u(ar1[4]);
            }
            uint32_t bf[8][2];
#pragma unroll
            for (int nt = 0; nt < 8; nt++) {
                bf[nt][0] = __float_as_uint(Bb[(kk * 8 + t) * PB_ST + n0 + nt * 8 + g]);
                bf[nt][1] = __float_as_uint(Bb[(kk * 8 + t + 4) * PB_ST + n0 + nt * 8 + g]);
            }
#pragma unroll
            for (int mi = 0; mi < 2; mi++)
#pragma unroll
                for (int nt = 0; nt < 8; nt++)
                    mma_tf32(acc[mi][nt], af[mi], bf[nt]);
        }
        // single barrier per step: next step's barrier precedes restage of this slot
    }

    // Epilogue: bias (+ReLU for V), convert bf16, store.
    const int h = (colBase + n0) >> 6;
#pragma unroll
    for (int mi = 0; mi < 2; mi++) {
        const int mr0 = rowBase + m0 + mi * 16 + g;
        const int mr1 = mr0 + 8;
        const int bb0 = mr0 >> 11, s0 = mr0 & 2047;
        const int bb1 = mr1 >> 11, s1 = mr1 & 2047;
        if (which < 2) {
            __nv_bfloat16* outb = (which == 0) ? g_Qb : g_Kb;
            __nv_bfloat16* o0 = &outb[((((size_t)bb0 * NUM_HEADS + h) * SEQ + s0) << 6)];
            __nv_bfloat16* o1 = &outb[((((size_t)bb1 * NUM_HEADS + h) * SEQ + s1) << 6)];
#pragma unroll
            for (int nt = 0; nt < 8; nt++) {
                const int n = colBase + n0 + nt * 8 + 2 * t;
                const int d = n & 63;
                const float bx = bias[n], by = bias[n + 1];
                *(uint32_t*)&o0[d] = pack_bf16x2(acc[mi][nt][0] + bx, acc[mi][nt][1] + by);
                *(uint32_t*)&o1[d] = pack_bf16x2(acc[mi][nt][2] + bx, acc[mi][nt][3] + by);
            }
        } else {
            // V: ReLU, transpose to [B,H,D,S]
#pragma unroll
            for (int nt = 0; nt < 8; nt++) {
                const int n = colBase + n0 + nt * 8 + 2 * t;
                const int d = n & 63;
                const float bx = bias[n], by = bias[n + 1];
                float v00 = fmaxf(acc[mi][nt][0] + bx, 0.f);
                float v01 = fmaxf(acc[mi][nt][1] + by, 0.f);
                float v10 = fmaxf(acc[mi][nt][2] + bx, 0.f);
                float v11 = fmaxf(acc[mi][nt][3] + by, 0.f);
                __nv_bfloat16* vt0 = &g_Vt[(((size_t)bb0 * NUM_HEADS + h) * HEAD_DIM + d) * SEQ + s0];
                __nv_bfloat16* vt1 = &g_Vt[(((size_t)bb1 * NUM_HEADS + h) * HEAD_DIM + d) * SEQ + s1];
                vt0[0]   = __float2bfloat16_rn(v00);
                vt0[SEQ] = __float2bfloat16_rn(v01);
                vt1[0]   = __float2bfloat16_rn(v10);
                vt1[SEQ] = __float2bfloat16_rn(v11);
            }
        }
    }
}

// ===========================================================================
// Flash attention, bf16 m16n8k16 — ROUND-12/15 CHAMPION STRUCTURE
// (2-stage cp.async double buffer, 55.3 KB smem, 2 CTAs/SM); only change: .cg.
// ===========================================================================
#define KSTH 72
#define KBUF_B (64 * KSTH * 2)            // 9216 B per K buffer
#define PATCH_B (16 * KSTH * 2)           // 2304 B per warp
#define AQR 128
#define ASMEM (2 * KBUF_B + 2 * KBUF_B + 8 * PATCH_B)   // 55296 B

__global__ __launch_bounds__(256, 2) void attn_mma_kernel(float* __restrict__ out)
{
    extern __shared__ char asmem[];
    const uint32_t ksb = smem_u32(asmem);                  // K: 2 x 64 x 72 bf16
    const uint32_t vsb = ksb + 2 * KBUF_B;                 // Vt: 2 x 64 x 72 bf16

    const int tid  = threadIdx.x;
    const int wid  = tid >> 5;
    const int lane = tid & 31;
    const int g    = lane >> 2;
    const int t    = lane & 3;
    const int bh   = blockIdx.y;
    const int qbase = blockIdx.x * AQR;

    uint32_t* patch32 = (uint32_t*)(asmem + (4 * KBUF_B) + wid * PATCH_B);

    const __nv_bfloat16* Qp = g_Qb + (size_t)bh * SEQ * 64 + (size_t)(qbase + wid * 16) * 64;
    const __nv_bfloat16* Kp = g_Kb + (size_t)bh * SEQ * 64;
    const __nv_bfloat16* Vtp = g_Vt + (size_t)bh * HEAD_DIM * SEQ;

    auto stage_kv = [&](int buf, int tile) {
#pragma unroll
        for (int i = 0; i < 2; i++) {
            const int idx = tid + i * 256;
            const int r = idx >> 3;
            const int j = idx & 7;
            cp16(ksb + buf * KBUF_B + r * 144 + j * 16,
                 &Kp[(size_t)(tile * 64 + r) * 64 + j * 8]);
        }
#pragma unroll
        for (int i = 0; i < 2; i++) {
            const int idx = tid + i * 256;
            const int d = idx >> 3;
            const int j = idx & 7;
            cp16(vsb + buf * KBUF_B + d * 144 + j * 16,
                 &Vtp[(size_t)d * SEQ + tile * 64 + j * 8]);
        }
        CP_COMMIT();
    };

    // Persistent Q a-frags (bf16x2 words straight from gmem).
    const uint32_t* Qw = (const uint32_t*)Qp;
    uint32_t qf[4][4];
#pragma unroll
    for (int kt = 0; kt < 4; ++kt) {
        qf[kt][0] = Qw[g * 32 + kt * 8 + t];
        qf[kt][1] = Qw[(g + 8) * 32 + kt * 8 + t];
        qf[kt][2] = Qw[g * 32 + kt * 8 + t + 4];
        qf[kt][3] = Qw[(g + 8) * 32 + kt * 8 + t + 4];
    }

    float O[8][4];
#pragma unroll
    for (int nt = 0; nt < 8; ++nt)
#pragma unroll
        for (int j = 0; j < 4; ++j) O[nt][j] = 0.f;

    float m0 = -1e30f, m1 = -1e30f, l0 = 0.f, l1 = 0.f;
    const float scale = 0.125f;

    stage_kv(0, 0);

    const uint32_t* Ks32base = (const uint32_t*)asmem;
    const uint32_t* Vs32base = (const uint32_t*)(asmem + 2 * KBUF_B);

    for (int it = 0; it < SEQ / 64; ++it) {
        const int buf = it & 1;
        if (it + 1 < SEQ / 64) {
            stage_kv(buf ^ 1, it + 1);
            CP_WAIT(1);
        } else {
            CP_WAIT(0);
        }
        __syncthreads();

        const uint32_t* Ks32 = Ks32base + buf * (KBUF_B / 4);   // row stride 36 words
        const uint32_t* Vs32 = Vs32base + buf * (KBUF_B / 4);

        // ---- S = Q @ K^T
        float SA[8][4];
#pragma unroll
        for (int nt = 0; nt < 8; ++nt)
#pragma unroll
            for (int j = 0; j < 4; ++j) SA[nt][j] = 0.f;

#pragma unroll
        for (int kt = 0; kt < 4; ++kt) {
#pragma unroll
            for (int nt = 0; nt < 8; ++nt) {
                uint32_t kb[2];
                const uint32_t* kr = &Ks32[(nt * 8 + g) * 36 + kt * 8 + t];
                kb[0] = kr[0];
                kb[1] = kr[4];
                mma_bf16(SA[nt], qf[kt], kb);
            }
        }

        // ---- Register online softmax.
        float mr0 = SA[0][0], mr1 = SA[0][2];
#pragma unroll
        for (int nt = 0; nt < 8; ++nt) {
            mr0 = fmaxf(mr0, fmaxf(SA[nt][0], SA[nt][1]));
            mr1 = fmaxf(mr1, fmaxf(SA[nt][2], SA[nt][3]));
        }
        mr0 = fmaxf(mr0, __shfl_xor_sync(0xffffffffu, mr0, 1));
        mr0 = fmaxf(mr0, __shfl_xor_sync(0xffffffffu, mr0, 2));
        mr1 = fmaxf(mr1, __shfl_xor_sync(0xffffffffu, mr1, 1));
        mr1 = fmaxf(mr1, __shfl_xor_sync(0xffffffffu, mr1, 2));

        const float mnew0 = fmaxf(m0, mr0 * scale);
        const float mnew1 = fmaxf(m1, mr1 * scale);
        const float fac0  = __expf(m0 - mnew0);
        const float fac1  = __expf(m1 - mnew1);

        float sum0 = 0.f, sum1 = 0.f;
#pragma unroll
        for (int nt = 0; nt < 8; ++nt) {
            const float p00 = __expf(SA[nt][0] * scale - mnew0);
            const float p01 = __expf(SA[nt][1] * scale - mnew0);
            const float p10 = __expf(SA[nt][2] * scale - mnew1);
            const float p11 = __expf(SA[nt][3] * scale - mnew1);
            sum0 += p00 + p01;
            sum1 += p10 + p11;
            patch32[g * 36 + nt * 4 + t]       = pack_bf16x2(p00, p01);
            patch32[(g + 8) * 36 + nt * 4 + t] = pack_bf16x2(p10, p11);
        }
        sum0 += __shfl_xor_sync(0xffffffffu, sum0, 1);
        sum0 += __shfl_xor_sync(0xffffffffu, sum0, 2);
        sum1 += __shfl_xor_sync(0xffffffffu, sum1, 1);
        sum1 += __shfl_xor_sync(0xffffffffu, sum1, 2);
        l0 = l0 * fac0 + sum0;
        l1 = l1 * fac1 + sum1;
        m0 = mnew0;
        m1 = mnew1;

#pragma unroll
        for (int nt = 0; nt < 8; ++nt) {
            O[nt][0] *= fac0; O[nt][1] *= fac0;
            O[nt][2] *= fac1; O[nt][3] *= fac1;
        }
        __syncwarp();

        // ---- O += P @ V
#pragma unroll
        for (int kt = 0; kt < 4; ++kt) {
            uint32_t pa[4];
            pa[0] = patch32[g * 36 + kt * 8 + t];
            pa[1] = patch32[(g + 8) * 36 + kt * 8 + t];
            pa[2] = patch32[g * 36 + kt * 8 + t + 4];
            pa[3] = patch32[(g + 8) * 36 + kt * 8 + t + 4];
#pragma unroll
            for (int nt = 0; nt < 8; ++nt) {
                uint32_t vb[2];
                const uint32_t* vr = &Vs32[(nt * 8 + g) * 36 + kt * 8 + t];
                vb[0] = vr[0];
                vb[1] = vr[4];
                mma_bf16(O[nt], pa, vb);
            }
        }
        __syncthreads();
    }

    // ---- Epilogue (fp32 out).
    const int b = bh >> 4;
    const int h = bh & 15;
    const float inv0 = 1.f / l0;
    const float inv1 = 1.f / l1;
    const int r0 = qbase + wid * 16 + g;
    const int r1 = r0 + 8;
    float* o0 = &out[((size_t)(b * SEQ + r0)) * DIM + h * 64];
    float* o1 = &out[((size_t)(b * SEQ + r1)) * DIM + h * 64];
#pragma unroll
    for (int nt = 0; nt < 8; ++nt) {
        *(float2*)&o0[nt * 8 + 2 * t] = make_float2(O[nt][0] * inv0, O[nt][1] * inv0);
        *(float2*)&o1[nt * 8 + 2 * t] = make_float2(O[nt][2] * inv1, O[nt][3] * inv1);
    }
}

// ===========================================================================
extern "C" void kernel_launch(void* const* d_in, const int* in_sizes, int n_in,
                              void* d_out, int out_size)
{
    const float* q  = (const float*)d_in[0];
    const float* k  = (const float*)d_in[1];
    const float* v  = (const float*)d_in[2];
    const float* Wq = (const float*)d_in[3];
    const float* bq = (const float*)d_in[4];
    const float* Wk = (const float*)d_in[5];
    const float* bk = (const float*)d_in[6];
    const float* Wv = (const float*)d_in[7];
    const float* bv = (const float*)d_in[8];
    float* out = (float*)d_out;

    cudaFuncSetAttribute(proj_mma_kernel, cudaFuncAttributeMaxDynamicSharedMemorySize, PJ_SMEM);
    cudaFuncSetAttribute(attn_mma_kernel, cudaFuncAttributeMaxDynamicSharedMemorySize, ASMEM);

    float* Wr;
    cudaGetSymbolAddress((void**)&Wr, g_Wr);
    const int nW4 = DIM * DIM / 4;

    round_copy3_kernel<<<1184, 256>>>((const float4*)Wq, (const float4*)Wk,
                                      (const float4*)Wv, (float4*)Wr, nW4);

    dim3 pgrid(DIM / 128, (B_SZ * SEQ) / 128, 3);    // (8, 64, 3)
    proj_mma_kernel<<<pgrid, 256, PJ_SMEM>>>(q, k, v, bq, bk, bv);

    dim3 agrid(SEQ / AQR, B_SZ * NUM_HEADS);         // (16, 64)
    attn_mma_kernel<<<agrid, 256, ASMEM>>>(out);
}

// round 17
// speedup vs baseline: 1.0597x; 1.0597x over previous
#include <cuda_runtime.h>
#include <cuda_bf16.h>
#include <cstdint>

#define NUM_HEADS 16
#define HEAD_DIM  64
#define B_SZ      4
#define SEQ       2048
#define DIM       1024

// Scratch (no cudaMalloc allowed).
__device__ __nv_bfloat16 g_Qb[B_SZ * SEQ * DIM];   // [B,H,S,D] bf16
__device__ __nv_bfloat16 g_Kb[B_SZ * SEQ * DIM];   // [B,H,S,D] bf16
__device__ __nv_bfloat16 g_Vt[B_SZ * SEQ * DIM];   // [B,H,D,S] bf16 (transposed)
__device__ float g_Wr[3 * DIM * DIM];              // RNA-rounded weights (q,k,v)

__device__ __forceinline__ float f2tf32f(float x) {
    uint32_t u;
    asm("cvt.rna.tf32.f32 %0, %1;" : "=r"(u) : "f"(x));
    return __uint_as_float(u);
}
__device__ __forceinline__ uint32_t f2tf32u(float x) {
    uint32_t u;
    asm("cvt.rna.tf32.f32 %0, %1;" : "=r"(u) : "f"(x));
    return u;
}
__device__ __forceinline__ uint32_t smem_u32(const void* p) {
    uint32_t a;
    asm("{ .reg .u64 t; cvta.to.shared.u64 t, %1; cvt.u32.u64 %0, t; }" : "=r"(a) : "l"(p));
    return a;
}
__device__ __forceinline__ void cp16(uint32_t s, const void* g) {
    asm volatile("cp.async.ca.shared.global [%0], [%1], 16;" :: "r"(s), "l"(g));
}
#define CP_COMMIT() asm volatile("cp.async.commit_group;" ::: "memory")
#define CP_WAIT(n)  asm volatile("cp.async.wait_group %0;" :: "n"(n) : "memory")

// tf32 MMA m16n8k8 (A row, B col), fp32 accum in place.
__device__ __forceinline__ void mma_tf32(float d[4], const uint32_t a[4], const uint32_t b[2]) {
    asm volatile(
        "mma.sync.aligned.m16n8k8.row.col.f32.tf32.tf32.f32 "
        "{%0,%1,%2,%3}, {%4,%5,%6,%7}, {%8,%9}, {%0,%1,%2,%3};"
        : "+f"(d[0]), "+f"(d[1]), "+f"(d[2]), "+f"(d[3])
        : "r"(a[0]), "r"(a[1]), "r"(a[2]), "r"(a[3]), "r"(b[0]), "r"(b[1]));
}
// bf16 MMA m16n8k16 (A row, B col), fp32 accum in place.
__device__ __forceinline__ void mma_bf16(float d[4], const uint32_t a[4], const uint32_t b[2]) {
    asm volatile(
        "mma.sync.aligned.m16n8k16.row.col.f32.bf16.bf16.f32 "
        "{%0,%1,%2,%3}, {%4,%5,%6,%7}, {%8,%9}, {%0,%1,%2,%3};"
        : "+f"(d[0]), "+f"(d[1]), "+f"(d[2]), "+f"(d[3])
        : "r"(a[0]), "r"(a[1]), "r"(a[2]), "r"(a[3]), "r"(b[0]), "r"(b[1]));
}
__device__ __forceinline__ uint32_t pack_bf16x2(float lo, float hi) {
    __nv_bfloat162 p = __float22bfloat162_rn(make_float2(lo, hi));
    return *(uint32_t*)&p;
}

// ===========================================================================
// Fused RNA tf32 rounding copy for all three weights (12MB total).
// ===========================================================================
__global__ __launch_bounds__(256) void round_copy3_kernel(
    const float4* __restrict__ s0, const float4* __restrict__ s1,
    const float4* __restrict__ s2, float4* __restrict__ dst, int n4)
{
    const int total = 3 * n4;
    for (int i = blockIdx.x * 256 + threadIdx.x; i < total; i += gridDim.x * 256) {
        const int which = i / n4;
        const int j = i - which * n4;
        const float4* src = (which == 0) ? s0 : ((which == 1) ? s1 : s2);
        float4 v = src[j];
        v.x = f2tf32f(v.x); v.y = f2tf32f(v.y);
        v.z = f2tf32f(v.z); v.w = f2tf32f(v.w);
        dst[i] = v;
    }
}

// ===========================================================================
// Fused projection GEMM (blockIdx.z = which), tf32 mma.sync.
// ROUND-15 CHAMPION STRUCTURE: 2-stage cp.async double buffer (.ca),
// stage-before-wait, two syncthreads per K-step, 71.7 KB smem.
// Outputs bf16: Q,K -> [B,H,S,D]; V -> [B,H,D,S] (transposed) with ReLU.
// ===========================================================================
#define PA_ST 36
#define PB_ST 136
#define PJ_ABUF (128 * PA_ST)
#define PJ_BBUF (32 * PB_ST)
#define PJ_SMEM ((2 * PJ_ABUF + 2 * PJ_BBUF) * 4)   // 71680 B

__global__ __launch_bounds__(256, 2) void proj_mma_kernel(
    const float* __restrict__ q, const float* __restrict__ k,
    const float* __restrict__ v,
    const float* __restrict__ bq, const float* __restrict__ bk,
    const float* __restrict__ bv)
{
    extern __shared__ float psm[];
    float* As = psm;                                 // 2 x 128 x 36
    float* Bs = psm + 2 * PJ_ABUF;                   // 2 x 32 x 136

    const int which = blockIdx.z;
    const float* A    = (which == 0) ? q  : ((which == 1) ? k  : v);
    const float* bias = (which == 0) ? bq : ((which == 1) ? bk : bv);
    const float* W    = g_Wr + (size_t)which * DIM * DIM;

    const int tid  = threadIdx.x;
    const int wid  = tid >> 5;
    const int lane = tid & 31;
    const int g    = lane >> 2;
    const int t    = lane & 3;
    const int warpM = wid >> 1;
    const int warpN = wid & 1;
    const int rowBase = blockIdx.y * 128;
    const int colBase = blockIdx.x * 128;

    float acc[2][8][4];
#pragma unroll
    for (int mi = 0; mi < 2; mi++)
#pragma unroll
        for (int nt = 0; nt < 8; nt++)
#pragma unroll
            for (int j = 0; j < 4; j++) acc[mi][nt][j] = 0.f;

    const uint32_t asb = smem_u32(As);
    const uint32_t bsb = smem_u32(Bs);

    auto stage = [&](int buf, int k0) {
#pragma unroll
        for (int i = 0; i < 4; i++) {
            const int idx = tid + i * 256;
            const int r  = idx >> 3;
            const int c4 = (idx & 7) << 2;
            cp16(asb + (buf * PJ_ABUF + r * PA_ST + c4) * 4,
                 &A[(size_t)(rowBase + r) * DIM + k0 + c4]);
        }
#pragma unroll
        for (int i = 0; i < 4; i++) {
            const int idx = tid + i * 256;
            const int r  = idx >> 5;
            const int c4 = (idx & 31) << 2;
            cp16(bsb + (buf * PJ_BBUF + r * PB_ST + c4) * 4,
                 &W[(size_t)(k0 + r) * DIM + colBase + c4]);
        }
        CP_COMMIT();
    };

    stage(0, 0);

    const int m0 = warpM * 32;
    const int n0 = warpN * 64;

    for (int step = 0; step < DIM / 32; ++step) {
        const int buf = step & 1;
        if (step + 1 < DIM / 32) {
            stage(buf ^ 1, (step + 1) * 32);
            CP_WAIT(1);
        } else {
            CP_WAIT(0);
        }
        __syncthreads();

        const float* Ab = As + buf * PJ_ABUF;
        const float* Bb = Bs + buf * PJ_BBUF;

#pragma unroll
        for (int kk = 0; kk < 4; ++kk) {
            uint32_t af[2][4];
#pragma unroll
            for (int mi = 0; mi < 2; mi++) {
                const float* ar0 = &Ab[(m0 + mi * 16 + g) * PA_ST + kk * 8 + t];
                const float* ar1 = &Ab[(m0 + mi * 16 + g + 8) * PA_ST + kk * 8 + t];
                af[mi][0] = f2tf32u(ar0[0]);
                af[mi][1] = f2tf32u(ar1[0]);
                af[mi][2] = f2tf32u(ar0[4]);
                af[mi][3] = f2tf32u(ar1[4]);
            }
            uint32_t bf[8][2];
#pragma unroll
            for (int nt = 0; nt < 8; nt++) {
                bf[nt][0] = __float_as_uint(Bb[(kk * 8 + t) * PB_ST + n0 + nt * 8 + g]);
                bf[nt][1] = __float_as_uint(Bb[(kk * 8 + t + 4) * PB_ST + n0 + nt * 8 + g]);
            }
#pragma unroll
            for (int mi = 0; mi < 2; mi++)
#pragma unroll
                for (int nt = 0; nt < 8; nt++)
                    mma_tf32(acc[mi][nt], af[mi], bf[nt]);
        }
        __syncthreads();
    }

    // Epilogue: bias (+ReLU for V), convert bf16, store.
    const int h = (colBase + n0) >> 6;
#pragma unroll
    for (int mi = 0; mi < 2; mi++) {
        const int mr0 = rowBase + m0 + mi * 16 + g;
        const int mr1 = mr0 + 8;
        const int bb0 = mr0 >> 11, s0 = mr0 & 2047;
        const int bb1 = mr1 >> 11, s1 = mr1 & 2047;
        if (which < 2) {
            __nv_bfloat16* outb = (which == 0) ? g_Qb : g_Kb;
            __nv_bfloat16* o0 = &outb[((((size_t)bb0 * NUM_HEADS + h) * SEQ + s0) << 6)];
            __nv_bfloat16* o1 = &outb[((((size_t)bb1 * NUM_HEADS + h) * SEQ + s1) << 6)];
#pragma unroll
            for (int nt = 0; nt < 8; nt++) {
                const int n = colBase + n0 + nt * 8 + 2 * t;
                const int d = n & 63;
                const float bx = bias[n], by = bias[n + 1];
                *(uint32_t*)&o0[d] = pack_bf16x2(acc[mi][nt][0] + bx, acc[mi][nt][1] + by);
                *(uint32_t*)&o1[d] = pack_bf16x2(acc[mi][nt][2] + bx, acc[mi][nt][3] + by);
            }
        } else {
            // V: ReLU, transpose to [B,H,D,S]
#pragma unroll
            for (int nt = 0; nt < 8; nt++) {
                const int n = colBase + n0 + nt * 8 + 2 * t;
                const int d = n & 63;
                const float bx = bias[n], by = bias[n + 1];
                float v00 = fmaxf(acc[mi][nt][0] + bx, 0.f);
                float v01 = fmaxf(acc[mi][nt][1] + by, 0.f);
                float v10 = fmaxf(acc[mi][nt][2] + bx, 0.f);
                float v11 = fmaxf(acc[mi][nt][3] + by, 0.f);
                __nv_bfloat16* vt0 = &g_Vt[(((size_t)bb0 * NUM_HEADS + h) * HEAD_DIM + d) * SEQ + s0];
                __nv_bfloat16* vt1 = &g_Vt[(((size_t)bb1 * NUM_HEADS + h) * HEAD_DIM + d) * SEQ + s1];
                vt0[0]   = __float2bfloat16_rn(v00);
                vt0[SEQ] = __float2bfloat16_rn(v01);
                vt1[0]   = __float2bfloat16_rn(v10);
                vt1[SEQ] = __float2bfloat16_rn(v11);
            }
        }
    }
}

// ===========================================================================
// Flash attention, bf16 m16n8k16, REGISTER-RESIDENT P (FlashAttention-2
// style): the PV A-fragments are the exp'd score registers packed to bf16x2 —
// accumulator cols (g, nt*8+2t..) of n-tiles {2kt,2kt+1} ARE A-frag rows/cols
// (g,2t),(g+8,2t),(g,2t+8),(g+8,2t+8) of kv-chunk kt. No P smem round-trip,
// no per-warp patch, no syncwarp. Smem: 4 x 9216 = 36.9 KB (2 CTAs/SM).
// ===========================================================================
#define KSTH 72
#define KBUF_B (64 * KSTH * 2)            // 9216 B per K buffer
#define AQR 128
#define ASMEM (4 * KBUF_B)                // 36864 B

__global__ __launch_bounds__(256, 2) void attn_mma_kernel(float* __restrict__ out)
{
    extern __shared__ char asmem[];
    const uint32_t ksb = smem_u32(asmem);                  // K: 2 x 64 x 72 bf16
    const uint32_t vsb = ksb + 2 * KBUF_B;                 // Vt: 2 x 64 x 72 bf16

    const int tid  = threadIdx.x;
    const int wid  = tid >> 5;
    const int lane = tid & 31;
    const int g    = lane >> 2;
    const int t    = lane & 3;
    const int bh   = blockIdx.y;
    const int qbase = blockIdx.x * AQR;

    const __nv_bfloat16* Qp = g_Qb + (size_t)bh * SEQ * 64 + (size_t)(qbase + wid * 16) * 64;
    const __nv_bfloat16* Kp = g_Kb + (size_t)bh * SEQ * 64;
    const __nv_bfloat16* Vtp = g_Vt + (size_t)bh * HEAD_DIM * SEQ;

    auto stage_kv = [&](int buf, int tile) {
#pragma unroll
        for (int i = 0; i < 2; i++) {
            const int idx = tid + i * 256;
            const int r = idx >> 3;
            const int j = idx & 7;
            cp16(ksb + buf * KBUF_B + r * 144 + j * 16,
                 &Kp[(size_t)(tile * 64 + r) * 64 + j * 8]);
        }
#pragma unroll
        for (int i = 0; i < 2; i++) {
            const int idx = tid + i * 256;
            const int d = idx >> 3;
            const int j = idx & 7;
            cp16(vsb + buf * KBUF_B + d * 144 + j * 16,
                 &Vtp[(size_t)d * SEQ + tile * 64 + j * 8]);
        }
        CP_COMMIT();
    };

    // Persistent Q a-frags (bf16x2 words straight from gmem).
    const uint32_t* Qw = (const uint32_t*)Qp;
    uint32_t qf[4][4];
#pragma unroll
    for (int kt = 0; kt < 4; ++kt) {
        qf[kt][0] = Qw[g * 32 + kt * 8 + t];
        qf[kt][1] = Qw[(g + 8) * 32 + kt * 8 + t];
        qf[kt][2] = Qw[g * 32 + kt * 8 + t + 4];
        qf[kt][3] = Qw[(g + 8) * 32 + kt * 8 + t + 4];
    }

    float O[8][4];
#pragma unroll
    for (int nt = 0; nt < 8; ++nt)
#pragma unroll
        for (int j = 0; j < 4; ++j) O[nt][j] = 0.f;

    float m0 = -1e30f, m1 = -1e30f, l0 = 0.f, l1 = 0.f;
    const float scale = 0.125f;

    stage_kv(0, 0);

    const uint32_t* Ks32base = (const uint32_t*)asmem;
    const uint32_t* Vs32base = (const uint32_t*)(asmem + 2 * KBUF_B);

    for (int it = 0; it < SEQ / 64; ++it) {
        const int buf = it & 1;
        if (it + 1 < SEQ / 64) {
            stage_kv(buf ^ 1, it + 1);
            CP_WAIT(1);
        } else {
            CP_WAIT(0);
        }
        __syncthreads();

        const uint32_t* Ks32 = Ks32base + buf * (KBUF_B / 4);   // row stride 36 words
        const uint32_t* Vs32 = Vs32base + buf * (KBUF_B / 4);

        // ---- S = Q @ K^T
        float SA[8][4];
#pragma unroll
        for (int nt = 0; nt < 8; ++nt)
#pragma unroll
            for (int j = 0; j < 4; ++j) SA[nt][j] = 0.f;

#pragma unroll
        for (int kt = 0; kt < 4; ++kt) {
#pragma unroll
            for (int nt = 0; nt < 8; ++nt) {
                uint32_t kb[2];
                const uint32_t* kr = &Ks32[(nt * 8 + g) * 36 + kt * 8 + t];
                kb[0] = kr[0];
                kb[1] = kr[4];
                mma_bf16(SA[nt], qf[kt], kb);
            }
        }

        // ---- Register online softmax (rows g, g+8; cols nt*8+2t, +2t+1).
        float mr0 = SA[0][0], mr1 = SA[0][2];
#pragma unroll
        for (int nt = 0; nt < 8; ++nt) {
            mr0 = fmaxf(mr0, fmaxf(SA[nt][0], SA[nt][1]));
            mr1 = fmaxf(mr1, fmaxf(SA[nt][2], SA[nt][3]));
        }
        mr0 = fmaxf(mr0, __shfl_xor_sync(0xffffffffu, mr0, 1));
        mr0 = fmaxf(mr0, __shfl_xor_sync(0xffffffffu, mr0, 2));
        mr1 = fmaxf(mr1, __shfl_xor_sync(0xffffffffu, mr1, 1));
        mr1 = fmaxf(mr1, __shfl_xor_sync(0xffffffffu, mr1, 2));

        const float mnew0 = fmaxf(m0, mr0 * scale);
        const float mnew1 = fmaxf(m1, mr1 * scale);
        const float fac0  = __expf(m0 - mnew0);
        const float fac1  = __expf(m1 - mnew1);

        float sum0 = 0.f, sum1 = 0.f;
#pragma unroll
        for (int nt = 0; nt < 8; ++nt) {
            const float p00 = __expf(SA[nt][0] * scale - mnew0);
            const float p01 = __expf(SA[nt][1] * scale - mnew0);
            const float p10 = __expf(SA[nt][2] * scale - mnew1);
            const float p11 = __expf(SA[nt][3] * scale - mnew1);
            sum0 += p00 + p01;
            sum1 += p10 + p11;
            SA[nt][0] = p00; SA[nt][1] = p01;    // P kept in registers
            SA[nt][2] = p10; SA[nt][3] = p11;
        }
        sum0 += __shfl_xor_sync(0xffffffffu, sum0, 1);
        sum0 += __shfl_xor_sync(0xffffffffu, sum0, 2);
        sum1 += __shfl_xor_sync(0xffffffffu, sum1, 1);
        sum1 += __shfl_xor_sync(0xffffffffu, sum1, 2);
        l0 = l0 * fac0 + sum0;
        l1 = l1 * fac1 + sum1;
        m0 = mnew0;
        m1 = mnew1;

#pragma unroll
        for (int nt = 0; nt < 8; ++nt) {
            O[nt][0] *= fac0; O[nt][1] *= fac0;
            O[nt][2] *= fac1; O[nt][3] *= fac1;
        }

        // ---- O += P @ V, P a-frags built from score registers directly.
        // kv-chunk kt (cols kt*16..+15) = n-tiles 2kt (lo 8) and 2kt+1 (hi 8):
        //   a0=(g, 2t,2t+1)lo  a1=(g+8, ..)lo  a2=(g, ..)hi  a3=(g+8, ..)hi
#pragma unroll
        for (int kt = 0; kt < 4; ++kt) {
            uint32_t pa[4];
            pa[0] = pack_bf16x2(SA[2 * kt][0],     SA[2 * kt][1]);
            pa[1] = pack_bf16x2(SA[2 * kt][2],     SA[2 * kt][3]);
            pa[2] = pack_bf16x2(SA[2 * kt + 1][0], SA[2 * kt + 1][1]);
            pa[3] = pack_bf16x2(SA[2 * kt + 1][2], SA[2 * kt + 1][3]);
#pragma unroll
            for (int nt = 0; nt < 8; ++nt) {
                uint32_t vb[2];
                const uint32_t* vr = &Vs32[(nt * 8 + g) * 36 + kt * 8 + t];
                vb[0] = vr[0];
                vb[1] = vr[4];
                mma_bf16(O[nt], pa, vb);
            }
        }
        __syncthreads();
    }

    // ---- Epilogue (fp32 out).
    const int b = bh >> 4;
    const int h = bh & 15;
    const float inv0 = 1.f / l0;
    const float inv1 = 1.f / l1;
    const int r0 = qbase + wid * 16 + g;
    const int r1 = r0 + 8;
    float* o0 = &out[((size_t)(b * SEQ + r0)) * DIM + h * 64];
    float* o1 = &out[((size_t)(b * SEQ + r1)) * DIM + h * 64];
#pragma unroll
    for (int nt = 0; nt < 8; ++nt) {
        *(float2*)&o0[nt * 8 + 2 * t] = make_float2(O[nt][0] * inv0, O[nt][1] * inv0);
        *(float2*)&o1[nt * 8 + 2 * t] = make_float2(O[nt][2] * inv1, O[nt][3] * inv1);
    }
}

// ===========================================================================
extern "C" void kernel_launch(void* const* d_in, const int* in_sizes, int n_in,
                              void* d_out, int out_size)
{
    const float* q  = (const float*)d_in[0];
    const float* k  = (const float*)d_in[1];
    const float* v  = (const float*)d_in[2];
    const float* Wq = (const float*)d_in[3];
    const float* bq = (const float*)d_in[4];
    const float* Wk = (const float*)d_in[5];
    const float* bk = (const float*)d_in[6];
    const float* Wv = (const float*)d_in[7];
    const float* bv = (const float*)d_in[8];
    float* out = (float*)d_out;

    cudaFuncSetAttribute(proj_mma_kernel, cudaFuncAttributeMaxDynamicSharedMemorySize, PJ_SMEM);
    cudaFuncSetAttribute(attn_mma_kernel, cudaFuncAttributeMaxDynamicSharedMemorySize, ASMEM);

    float* Wr;
    cudaGetSymbolAddress((void**)&Wr, g_Wr);
    const int nW4 = DIM * DIM / 4;

    round_copy3_kernel<<<1184, 256>>>((const float4*)Wq, (const float4*)Wk,
                                      (const float4*)Wv, (float4*)Wr, nW4);

    dim3 pgrid(DIM / 128, (B_SZ * SEQ) / 128, 3);    // (8, 64, 3)
    proj_mma_kernel<<<pgrid, 256, PJ_SMEM>>>(q, k, v, bq, bk, bv);

    dim3 agrid(SEQ / AQR, B_SZ * NUM_HEADS);         // (16, 64)
    attn_mma_kernel<<<agrid, 256, ASMEM>>>(out);
}